// round 13
// baseline (speedup 1.0000x reference)
#include <cuda_runtime.h>
#include <math.h>

// Problem constants
#define BB 4
#define MM 500   // rows (pred2)
#define NN 500   // cols (pred1)
#define CC 91
#define NPAD 512
#define FULLMASK 0xffffffffu
#define MARGIN 1e-4f

// Scratch (device globals; no allocation allowed)
__device__ float g_s1[BB * NN * CC];   // sigmoid(pred1_logits)
__device__ float g_s2[BB * MM * CC];   // sigmoid(pred2_logits)
__device__ __align__(16) float g_cost[BB * MM * NPAD]; // padded cost rows
__device__ int   g_map[BB * MM];       // row -> col assignment

// ---------------------------------------------------------------------------
// 1) sigmoids
// ---------------------------------------------------------------------------
__global__ void sigmoid_kernel(const float* __restrict__ l1,
                               const float* __restrict__ l2) {
    int idx = blockIdx.x * blockDim.x + threadIdx.x;
    const int n1 = BB * NN * CC;
    const int n2 = BB * MM * CC;
    if (idx < n1) {
        float x = l1[idx];
        g_s1[idx] = 1.0f / (1.0f + expf(-x));
    } else if (idx < n1 + n2) {
        float x = l2[idx - n1];
        g_s2[idx - n1] = 1.0f / (1.0f + expf(-x));
    }
}

// ---------------------------------------------------------------------------
// 2) cost matrix: cost[b][i][j] = 0.5*||c2_i - c1_j||2 + 0.5*max_c|s2-s1|
// ---------------------------------------------------------------------------
__global__ __launch_bounds__(1024) void cost_kernel(
        const float* __restrict__ p1_boxes,
        const float* __restrict__ p2_boxes) {
    const int b = blockIdx.z;
    const int i0 = blockIdx.y * 32;
    const int j0 = blockIdx.x * 32;

    __shared__ float s2t[32][CC];
    __shared__ float s1t[32][CC];
    __shared__ float b2x[32], b2y[32], b1x[32], b1y[32];

    const int tx = threadIdx.x;
    const int ty = threadIdx.y;
    const int tid = ty * 32 + tx;

    for (int idx = tid; idx < 32 * CC; idx += 1024) {
        int r = idx / CC, c = idx % CC;
        int gi = i0 + r;
        int gj = j0 + r;
        s2t[r][c] = (gi < MM) ? g_s2[(b * MM + gi) * CC + c] : 0.0f;
        s1t[r][c] = (gj < NN) ? g_s1[(b * NN + gj) * CC + c] : 0.0f;
    }
    if (ty == 0) {
        int gi = i0 + tx;
        if (gi < MM) {
            b2x[tx] = p2_boxes[(b * MM + gi) * 4 + 0];
            b2y[tx] = p2_boxes[(b * MM + gi) * 4 + 1];
        }
    } else if (ty == 1) {
        int gj = j0 + tx;
        if (gj < NN) {
            b1x[tx] = p1_boxes[(b * NN + gj) * 4 + 0];
            b1y[tx] = p1_boxes[(b * NN + gj) * 4 + 1];
        }
    }
    __syncthreads();

    const int i = i0 + ty;
    const int j = j0 + tx;
    if (i < MM) {
        if (j < NN) {
            float mx = 0.0f;
            #pragma unroll
            for (int c = 0; c < CC; c++) {
                mx = fmaxf(mx, fabsf(s2t[ty][c] - s1t[tx][c]));
            }
            float dx = __fadd_rn(b2x[ty], -b1x[tx]);
            float dy = __fadd_rn(b2y[ty], -b1y[tx]);
            float cd = __fsqrt_rn(__fadd_rn(__fmul_rn(dx, dx), __fmul_rn(dy, dy)));
            g_cost[(b * MM + i) * NPAD + j] =
                __fadd_rn(__fmul_rn(0.5f, cd), __fmul_rn(0.5f, mx));
        } else {
            g_cost[(b * MM + i) * NPAD + j] = 1e30f;  // padding
        }
    }
}

// ---------------------------------------------------------------------------
// merge helper for (min1, argmin1, min2, argmin2) pairs (fp64 exact)
// ---------------------------------------------------------------------------
__device__ __forceinline__ void merge_min2(double& m1, int& j1, double& m2, int& j2,
                                           double om1, int oj1, double om2, int oj2) {
    bool take = (om1 < m1) || (om1 == m1 && oj1 < j1);
    double lv = take ? m1 : om1;
    int    lj = take ? j1 : oj1;
    if (take) { m1 = om1; j1 = oj1; }
    if (om2 < m2) { m2 = om2; j2 = oj2; }
    if (lv < m2)  { m2 = lv;  j2 = lj; }
}

// ---------------------------------------------------------------------------
// 3) exact LSA (LAPJV): column reduction + augmenting row reduction with
//    correct dual maintenance (u[i] = m2 at assignment time => feasibility
//    AND matched-edge tightness hold invariantly) + shortest-augmenting-path
//    Dijkstra for remaining free rows (register-resident-key inner loop).
//    One warp per batch; lane L owns columns [L*16, L*16+16).
// ---------------------------------------------------------------------------
__global__ __launch_bounds__(32) void lsa_kernel() {
    const int b = blockIdx.x;
    const int lane = threadIdx.x;
    const double DINF = __longlong_as_double(0x7ff0000000000000LL);
    const float  FINF = __int_as_float(0x7f800000);

    __shared__ double u64s[MM];
    __shared__ double v64s[NPAD];
    __shared__ double s64s[NPAD];
    __shared__ float u32s[MM];
    __shared__ __align__(16) float v32s[NPAD];
    __shared__ __align__(16) float s32s[NPAD];
    __shared__ int paths[NPAD];
    __shared__ int col4rows[MM];
    __shared__ int row4cols[NPAD];
    __shared__ int SRs[MM];
    __shared__ int freeL[MM];
    __shared__ int sh_nf;

    for (int t = lane; t < NPAD; t += 32) {
        v64s[t] = 0.0; v32s[t] = 0.0f; row4cols[t] = -1;
        if (t < MM) { u64s[t] = 0.0; u32s[t] = 0.0f; col4rows[t] = -1; }
    }
    const int base = lane * 16;
    unsigned validMask;
    {
        int nvalid = NN - base;
        if (nvalid < 0) nvalid = 0;
        if (nvalid > 16) nvalid = 16;
        validMask = (nvalid == 16) ? 0xffffu : ((1u << nvalid) - 1u);
    }
    __syncwarp();

    const float* costB = g_cost + (size_t)b * MM * NPAD;

    // ------------------- Phase A: column reduction --------------------------
    {
        float vmin[16];
        int imin[16];
        #pragma unroll
        for (int kk = 0; kk < 16; kk++) { vmin[kk] = FINF; imin[kk] = 0; }
        for (int i = 0; i < MM; i++) {
            const float* crow = costB + (size_t)i * NPAD + base;
            float4 ca = __ldg((const float4*)(crow + 0));
            float4 cb = __ldg((const float4*)(crow + 4));
            float4 cc_ = __ldg((const float4*)(crow + 8));
            float4 cd = __ldg((const float4*)(crow + 12));
            float c[16];
            c[0]=ca.x; c[1]=ca.y; c[2]=ca.z; c[3]=ca.w;
            c[4]=cb.x; c[5]=cb.y; c[6]=cb.z; c[7]=cb.w;
            c[8]=cc_.x; c[9]=cc_.y; c[10]=cc_.z; c[11]=cc_.w;
            c[12]=cd.x; c[13]=cd.y; c[14]=cd.z; c[15]=cd.w;
            #pragma unroll
            for (int kk = 0; kk < 16; kk++) {
                if (c[kk] < vmin[kk]) { vmin[kk] = c[kk]; imin[kk] = i; }
            }
        }
        #pragma unroll
        for (int kk = 0; kk < 16; kk++) {
            int j = base + kk;
            if ((validMask >> kk) & 1u) {
                v64s[j] = (double)vmin[kk];   // exact
                v32s[j] = vmin[kk];
                paths[j] = imin[kk];          // temp: argmin row per column
            }
        }
        __syncwarp();
        if (lane == 0) {
            for (int j = NN - 1; j >= 0; j--) {
                int i1 = paths[j];
                if (col4rows[i1] == -1) {
                    col4rows[i1] = j;
                    row4cols[j] = i1;
                    // matched edge tight with u = 0: c[i1][j] - v[j] = 0 exactly
                }
            }
        }
        __syncwarp();
    }

    // --------- Phase A2: augmenting row reduction (2 passes, u = m2) --------
    for (int pass = 0; pass < 2; pass++) {
        if (lane == 0) {
            int nf = 0;
            for (int i2 = 0; i2 < MM; i2++)
                if (col4rows[i2] < 0) freeL[nf++] = i2;
            sh_nf = nf;
        }
        __syncwarp();
        const int nf = sh_nf;
        __syncwarp();
        int k = 0;
        int cnt = 0;
        while (k < nf && cnt < 4 * MM) {
            cnt++;
            int i = freeL[k]; k++;
            const float* crow = costB + (size_t)i * NPAD + base;
            float4 ca = __ldg((const float4*)(crow + 0));
            float4 cb = __ldg((const float4*)(crow + 4));
            float4 cc_ = __ldg((const float4*)(crow + 8));
            float4 cd = __ldg((const float4*)(crow + 12));
            float c[16];
            c[0]=ca.x; c[1]=ca.y; c[2]=ca.z; c[3]=ca.w;
            c[4]=cb.x; c[5]=cb.y; c[6]=cb.z; c[7]=cb.w;
            c[8]=cc_.x; c[9]=cc_.y; c[10]=cc_.z; c[11]=cc_.w;
            c[12]=cd.x; c[13]=cd.y; c[14]=cd.z; c[15]=cd.w;
            double m1 = DINF, m2 = DINF;
            int j1v = 0x7fffffff, j2v = 0x7fffffff;
            #pragma unroll
            for (int kk = 0; kk < 16; kk++) {
                if ((validMask >> kk) & 1u) {
                    int j = base + kk;
                    double d = (double)c[kk] - v64s[j];
                    if (d < m1 || (d == m1 && j < j1v)) {
                        m2 = m1; j2v = j1v;
                        m1 = d;  j1v = j;
                    } else if (d < m2) {
                        m2 = d; j2v = j;
                    }
                }
            }
            #pragma unroll
            for (int off = 16; off > 0; off >>= 1) {
                double om1 = __shfl_xor_sync(FULLMASK, m1, off);
                int    oj1 = __shfl_xor_sync(FULLMASK, j1v, off);
                double om2 = __shfl_xor_sync(FULLMASK, m2, off);
                int    oj2 = __shfl_xor_sync(FULLMASK, j2v, off);
                merge_min2(m1, j1v, m2, j2v, om1, oj1, om2, oj2);
            }
            bool strict = (m1 < m2);
            int jA = j1v;
            int i0 = row4cols[jA];
            if (!strict && i0 >= 0) {
                jA = j2v;                 // tie: take second column if first busy
                i0 = row4cols[jA];
            }
            __syncwarp();   // all reads done before lane0 writes
            if (lane == 0) {
                if (strict) {
                    // v[jA] := c[i][jA] - m2  (reduced cost at jA becomes m2)
                    double nv = v64s[jA] - (m2 - m1);
                    v64s[jA] = nv;
                    v32s[jA] = (float)nv;
                }
                // u[i] = m2: feasible (min over j != jA is m2) and tight at jA
                u64s[i] = m2;
                u32s[i] = (float)m2;
                if (i0 >= 0) col4rows[i0] = -1;   // displaced row is free
                col4rows[i] = jA;
                row4cols[jA] = i;
            }
            if (i0 >= 0 && strict) {
                k--;
                if (lane == 0) freeL[k] = i0;     // immediate retry
            }
            // tie-displaced rows (i0>=0 && !strict) are picked up next pass
            __syncwarp();
        }
        __syncwarp();
    }

    // free rows enter Dijkstra with u = 0 (always feasible: v <= colmin
    // initially and v only decreased since)
    if (lane == 0) {
        int nf = 0;
        for (int i2 = 0; i2 < MM; i2++)
            if (col4rows[i2] < 0) {
                freeL[nf++] = i2;
                u64s[i2] = 0.0;
                u32s[i2] = 0.0f;
            }
        sh_nf = nf;
    }
    __syncwarp();
    const int nfree = sh_nf;
    __syncwarp();

    // ------ Phase B: Dijkstra rounds (register-resident-key inner loop) -----
    for (int fidx = 0; fidx < nfree; fidx++) {
        const int cur = freeL[fidx];
        #pragma unroll
        for (int kk = 0; kk < 16; kk++) {
            int j = base + kk;
            s64s[j] = DINF;
            s32s[j] = FINF;
        }
        unsigned rem = validMask;
        unsigned scanned = 0;
        double minv = 0.0;
        float minv32 = 0.0f;
        int i = cur;
        int nSR = 0;
        int sink = -1;
        __syncwarp();

        while (true) {
            if (lane == 0) SRs[nSR] = i;
            nSR++;
            float dd32 = minv32 - u32s[i];
            const float* crow = costB + (size_t)i * NPAD + base;

            float4 c4[4];
            c4[0] = __ldg((const float4*)(crow + 0));
            c4[1] = __ldg((const float4*)(crow + 4));
            c4[2] = __ldg((const float4*)(crow + 8));
            c4[3] = __ldg((const float4*)(crow + 12));

            // fp32 sweep over owned columns; build candidate mask + packed key
            float se[16];
            unsigned candMask = 0;
            unsigned bestKey = 0xffffffffu;
            #pragma unroll
            for (int q = 0; q < 4; q++) {
                float4 vv = *(const float4*)(v32s + base + q * 4);
                float4 sv = *(const float4*)(s32s + base + q * 4);
                float cA[4] = {c4[q].x, c4[q].y, c4[q].z, c4[q].w};
                float vA[4] = {vv.x, vv.y, vv.z, vv.w};
                float sA[4] = {sv.x, sv.y, sv.z, sv.w};
                #pragma unroll
                for (int e = 0; e < 4; e++) {
                    int kk = q * 4 + e;
                    float r = (cA[e] - vA[e]) + dd32;
                    bool remb = (rem >> kk) & 1u;
                    bool cand = remb && (r < sA[e] + MARGIN);
                    if (cand) candMask |= (1u << kk);
                    float s_eff = cand ? fminf(sA[e], r) : sA[e];
                    se[kk] = s_eff;
                    unsigned ub = __float_as_uint(s_eff);
                    unsigned tkey = ub ^ (((unsigned)((int)ub >> 31)) | 0x80000000u);
                    unsigned key = (tkey & 0xfffffe00u) | (unsigned)(base + kk);
                    bestKey = min(bestKey, key);
                }
            }
            // exact fp64 updates for candidates only
            if (candMask) {
                double dd = minv - u64s[i];
                do {
                    int kk = __ffs(candMask) - 1;
                    candMask &= candMask - 1;
                    int j = base + kk;
                    double c64 = (double)__ldg(crow + kk);
                    double r = (c64 - v64s[j]) + dd;
                    if (r < s64s[j]) {
                        s64s[j] = r;
                        float rf = (float)r;
                        s32s[j] = rf;
                        paths[j] = i;
                        unsigned ub = __float_as_uint(rf);
                        unsigned tkey = ub ^ (((unsigned)((int)ub >> 31)) | 0x80000000u);
                        unsigned key = (tkey & 0xfffffe00u) | (unsigned)j;
                        bestKey = min(bestKey, key);
                    }
                } while (candMask);
            }
            // one REDUX: approximate min value + approximate argmin column
            unsigned mk = __reduce_min_sync(FULLMASK, bestKey);
            int jm_a = (int)(mk & 0x1ffu);
            unsigned tval = mk & 0xfffffe00u;
            float m32 = (tval & 0x80000000u) ? __uint_as_float(tval & 0x7fffffffu)
                                             : __uint_as_float(~tval);
            // speculative prefetch of the likely next row (own segment)
            int i_next = row4cols[jm_a];
            if (i_next >= 0) {
                const float* pf = costB + (size_t)i_next * NPAD + base;
                asm volatile("prefetch.global.L1 [%0];" :: "l"(pf));
            }
            // exact resolution among columns within threshold
            float thr = fmaf(6.2e-5f, fabsf(m32), m32 + MARGIN);
            unsigned resMask = 0;
            #pragma unroll
            for (int kk = 0; kk < 16; kk++) {
                if (se[kk] <= thr) resMask |= (1u << kk);
            }
            resMask &= rem;
            double bestV = DINF;
            int bestJ = 0x7fffffff;
            while (resMask) {
                int kk = __ffs(resMask) - 1;
                resMask &= resMask - 1;
                int j = base + kk;
                double sv = s64s[j];
                if (sv < bestV) { bestV = sv; bestJ = j; }  // ascending j
            }
            unsigned bal = __ballot_sync(FULLMASK, bestJ != 0x7fffffff);
            int jm;
            if (__popc(bal) == 1) {
                int src = __ffs(bal) - 1;
                minv = __shfl_sync(FULLMASK, bestV, src);
                jm   = __shfl_sync(FULLMASK, bestJ, src);
            } else {
                #pragma unroll
                for (int off = 16; off > 0; off >>= 1) {
                    double ov = __shfl_down_sync(FULLMASK, bestV, off);
                    int    oj = __shfl_down_sync(FULLMASK, bestJ, off);
                    if (ov < bestV || (ov == bestV && oj < bestJ)) { bestV = ov; bestJ = oj; }
                }
                minv = __shfl_sync(FULLMASK, bestV, 0);
                jm   = __shfl_sync(FULLMASK, bestJ, 0);
            }
            if (jm > 0x1ff) { sink = -1; break; }   // defensive
            minv32 = (float)minv;
            // remove column jm
            if (lane == (jm >> 4)) {
                rem &= ~(1u << (jm & 15));
                scanned |= (1u << (jm & 15));
                s32s[jm] = FINF;
            }
            int r4c = row4cols[jm];   // shared broadcast
            if (r4c < 0) { sink = jm; break; }
            i = r4c;
        }
        __syncwarp();
        if (sink < 0) continue;       // defensive (never taken in valid runs)

        // dual updates (exact fp64)
        for (int s = lane; s < nSR; s += 32) {
            int row = SRs[s];
            double nu = u64s[row] +
                        ((s == 0) ? minv : (minv - s64s[col4rows[row]]));
            u64s[row] = nu;
            u32s[row] = (float)nu;
        }
        {
            unsigned sm2 = scanned;
            while (sm2) {
                int kk = __ffs(sm2) - 1;
                sm2 &= sm2 - 1;
                int j = base + kk;
                double nv = v64s[j] - (minv - s64s[j]);
                v64s[j] = nv;
                v32s[j] = (float)nv;
            }
        }
        __syncwarp();
        if (lane == 0) {
            int j = sink;
            while (true) {
                int ii = paths[j];
                row4cols[j] = ii;
                int t = col4rows[ii];
                col4rows[ii] = j;
                j = t;
                if (ii == cur) break;
            }
        }
        __syncwarp();
    }

    for (int t = lane; t < MM; t += 32) g_map[b * MM + t] = col4rows[t];
}

// ---------------------------------------------------------------------------
// 4) extrapolation + output write
// ---------------------------------------------------------------------------
__global__ void extrap_kernel(const float* __restrict__ p1_boxes,
                              const float* __restrict__ p1_logits,
                              const float* __restrict__ p2_boxes,
                              const float* __restrict__ p2_logits,
                              const float* __restrict__ toff,
                              float* __restrict__ out) {
    int idx = blockIdx.x * blockDim.x + threadIdx.x;
    const int boxTotal = BB * MM * 4;
    const int logTotal = BB * MM * CC;
    if (idx < boxTotal) {
        int d = idx & 3;
        int bi = idx >> 2;
        int b = bi / MM;
        float first  = toff[b * 3 + 1] - toff[b * 3 + 0];
        float second = toff[b * 3 + 2] - toff[b * 3 + 1];
        float factor = second / first;
        int mcol = g_map[bi];
        float b2 = p2_boxes[idx];
        float c1 = p1_boxes[(b * NN + mcol) * 4 + d];
        float val = b2 + (b2 - c1) * factor;
        if (d >= 2) val = fmaxf(val, 0.0f);
        out[idx] = val;
    } else if (idx < boxTotal + logTotal) {
        int t = idx - boxTotal;
        int c = t % CC;
        int bi = t / CC;
        int b = bi / MM;
        int mcol = g_map[bi];
        float l2 = p2_logits[t];
        float l1 = p1_logits[(b * NN + mcol) * CC + c];
        out[idx] = 0.5f * (l2 + l1);
    }
}

// ---------------------------------------------------------------------------
extern "C" void kernel_launch(void* const* d_in, const int* in_sizes, int n_in,
                              void* d_out, int out_size) {
    const float* p1_boxes  = (const float*)d_in[0];
    const float* p1_logits = (const float*)d_in[1];
    const float* p2_boxes  = (const float*)d_in[2];
    const float* p2_logits = (const float*)d_in[3];
    const float* toff      = (const float*)d_in[4];
    float* out = (float*)d_out;

    {
        int total = BB * NN * CC + BB * MM * CC;
        int threads = 256;
        int blocks = (total + threads - 1) / threads;
        sigmoid_kernel<<<blocks, threads>>>(p1_logits, p2_logits);
    }
    {
        dim3 grid(NPAD / 32, (MM + 31) / 32, BB);
        dim3 block(32, 32);
        cost_kernel<<<grid, block>>>(p1_boxes, p2_boxes);
    }
    lsa_kernel<<<BB, 32>>>();
    {
        int total = BB * MM * 4 + BB * MM * CC;
        int threads = 256;
        int blocks = (total + threads - 1) / threads;
        extrap_kernel<<<blocks, threads>>>(p1_boxes, p1_logits, p2_boxes,
                                           p2_logits, toff, out);
    }
}

// round 14
// speedup vs baseline: 1.9282x; 1.9282x over previous
#include <cuda_runtime.h>
#include <math.h>

// Problem constants
#define BB 4
#define MM 500   // rows (pred2)
#define NN 500   // cols (pred1)
#define CC 91
#define NPAD 512
#define FULLMASK 0xffffffffu
#define MARGIN 1e-5f

// Scratch (device globals; no allocation allowed)
__device__ float g_s1[BB * NN * CC];   // sigmoid(pred1_logits)
__device__ float g_s2[BB * MM * CC];   // sigmoid(pred2_logits)
__device__ __align__(16) float g_cost[BB * MM * NPAD]; // padded cost rows
__device__ int   g_map[BB * MM];       // row -> col assignment

__device__ __forceinline__ long long pack_rcu(float u32v, int row) {
    return (long long)(((unsigned long long)__float_as_uint(u32v) << 32) |
                       (unsigned)row);
}

// ---------------------------------------------------------------------------
// 1) sigmoids
// ---------------------------------------------------------------------------
__global__ void sigmoid_kernel(const float* __restrict__ l1,
                               const float* __restrict__ l2) {
    int idx = blockIdx.x * blockDim.x + threadIdx.x;
    const int n1 = BB * NN * CC;
    const int n2 = BB * MM * CC;
    if (idx < n1) {
        float x = l1[idx];
        g_s1[idx] = 1.0f / (1.0f + expf(-x));
    } else if (idx < n1 + n2) {
        float x = l2[idx - n1];
        g_s2[idx - n1] = 1.0f / (1.0f + expf(-x));
    }
}

// ---------------------------------------------------------------------------
// 2) cost matrix: cost[b][i][j] = 0.5*||c2_i - c1_j||2 + 0.5*max_c|s2-s1|
// ---------------------------------------------------------------------------
__global__ __launch_bounds__(1024) void cost_kernel(
        const float* __restrict__ p1_boxes,
        const float* __restrict__ p2_boxes) {
    const int b = blockIdx.z;
    const int i0 = blockIdx.y * 32;
    const int j0 = blockIdx.x * 32;

    __shared__ float s2t[32][CC];
    __shared__ float s1t[32][CC];
    __shared__ float b2x[32], b2y[32], b1x[32], b1y[32];

    const int tx = threadIdx.x;
    const int ty = threadIdx.y;
    const int tid = ty * 32 + tx;

    for (int idx = tid; idx < 32 * CC; idx += 1024) {
        int r = idx / CC, c = idx % CC;
        int gi = i0 + r;
        int gj = j0 + r;
        s2t[r][c] = (gi < MM) ? g_s2[(b * MM + gi) * CC + c] : 0.0f;
        s1t[r][c] = (gj < NN) ? g_s1[(b * NN + gj) * CC + c] : 0.0f;
    }
    if (ty == 0) {
        int gi = i0 + tx;
        if (gi < MM) {
            b2x[tx] = p2_boxes[(b * MM + gi) * 4 + 0];
            b2y[tx] = p2_boxes[(b * MM + gi) * 4 + 1];
        }
    } else if (ty == 1) {
        int gj = j0 + tx;
        if (gj < NN) {
            b1x[tx] = p1_boxes[(b * NN + gj) * 4 + 0];
            b1y[tx] = p1_boxes[(b * NN + gj) * 4 + 1];
        }
    }
    __syncthreads();

    const int i = i0 + ty;
    const int j = j0 + tx;
    if (i < MM) {
        if (j < NN) {
            float mx = 0.0f;
            #pragma unroll
            for (int c = 0; c < CC; c++) {
                mx = fmaxf(mx, fabsf(s2t[ty][c] - s1t[tx][c]));
            }
            float dx = __fadd_rn(b2x[ty], -b1x[tx]);
            float dy = __fadd_rn(b2y[ty], -b1y[tx]);
            float cd = __fsqrt_rn(__fadd_rn(__fmul_rn(dx, dx), __fmul_rn(dy, dy)));
            g_cost[(b * MM + i) * NPAD + j] =
                __fadd_rn(__fmul_rn(0.5f, cd), __fmul_rn(0.5f, mx));
        } else {
            g_cost[(b * MM + i) * NPAD + j] = 1e30f;  // padding
        }
    }
}

// ---------------------------------------------------------------------------
// 3) exact LSA: column reduction (exact duals, u == 0) + shortest-augmenting-
//    path Dijkstra for free rows (register-resident-key inner loop = the
//    measured-fastest variant). One warp per batch; lane L owns columns
//    [L*16, L*16+16).
//    rcu[j] packs (u32 bits of u[row4col[j]], row4col[j]) so the selection
//    tail resolves next-row AND its u in a single LDS.64.
// ---------------------------------------------------------------------------
__global__ __launch_bounds__(32) void lsa_kernel() {
    const int b = blockIdx.x;
    const int lane = threadIdx.x;
    const double DINF = __longlong_as_double(0x7ff0000000000000LL);
    const float  FINF = __int_as_float(0x7f800000);

    __shared__ double u64s[MM];
    __shared__ double v64s[NPAD];
    __shared__ double s64s[NPAD];
    __shared__ float u32s[MM];
    __shared__ __align__(16) float v32s[NPAD];
    __shared__ __align__(16) float s32s[NPAD];
    __shared__ __align__(8) long long rcu[NPAD];  // (u32bits<<32)|row4col
    __shared__ int paths[NPAD];
    __shared__ int col4rows[MM];
    __shared__ int SRs[MM];
    __shared__ int freeL[MM];
    __shared__ int sh_nf;

    for (int t = lane; t < NPAD; t += 32) {
        v64s[t] = 0.0; v32s[t] = 0.0f;
        rcu[t] = 0xffffffffLL;                 // row=-1, u=0
        if (t < MM) { u64s[t] = 0.0; u32s[t] = 0.0f; col4rows[t] = -1; }
    }
    const int base = lane * 16;
    unsigned validMask;
    {
        int nvalid = NN - base;
        if (nvalid < 0) nvalid = 0;
        if (nvalid > 16) nvalid = 16;
        validMask = (nvalid == 16) ? 0xffffu : ((1u << nvalid) - 1u);
    }
    __syncwarp();

    const float* costB = g_cost + (size_t)b * MM * NPAD;

    // ------------------- Phase A: column reduction --------------------------
    {
        float vmin[16];
        int imin[16];
        #pragma unroll
        for (int kk = 0; kk < 16; kk++) { vmin[kk] = FINF; imin[kk] = 0; }
        for (int i = 0; i < MM; i++) {
            const float* crow = costB + (size_t)i * NPAD + base;
            float4 ca = __ldg((const float4*)(crow + 0));
            float4 cb = __ldg((const float4*)(crow + 4));
            float4 cc_ = __ldg((const float4*)(crow + 8));
            float4 cd = __ldg((const float4*)(crow + 12));
            float c[16];
            c[0]=ca.x; c[1]=ca.y; c[2]=ca.z; c[3]=ca.w;
            c[4]=cb.x; c[5]=cb.y; c[6]=cb.z; c[7]=cb.w;
            c[8]=cc_.x; c[9]=cc_.y; c[10]=cc_.z; c[11]=cc_.w;
            c[12]=cd.x; c[13]=cd.y; c[14]=cd.z; c[15]=cd.w;
            #pragma unroll
            for (int kk = 0; kk < 16; kk++) {
                if (c[kk] < vmin[kk]) { vmin[kk] = c[kk]; imin[kk] = i; }
            }
        }
        #pragma unroll
        for (int kk = 0; kk < 16; kk++) {
            int j = base + kk;
            if ((validMask >> kk) & 1u) {
                v64s[j] = (double)vmin[kk];   // exact
                v32s[j] = vmin[kk];
                paths[j] = imin[kk];          // temp: argmin row per column
            }
        }
        __syncwarp();
        if (lane == 0) {
            for (int j = NN - 1; j >= 0; j--) {
                int i1 = paths[j];
                if (col4rows[i1] == -1) {
                    col4rows[i1] = j;
                    rcu[j] = (long long)(unsigned)i1;   // u=0 bits, row=i1
                }
            }
            int nf = 0;
            for (int i2 = 0; i2 < MM; i2++)
                if (col4rows[i2] < 0) freeL[nf++] = i2;
            sh_nf = nf;
        }
        __syncwarp();
    }
    const int nfree = sh_nf;
    __syncwarp();

    // ------ Phase B: Dijkstra rounds (register-resident-key inner loop) -----
    for (int fidx = 0; fidx < nfree; fidx++) {
        const int cur = freeL[fidx];
        #pragma unroll
        for (int kk = 0; kk < 16; kk++) {
            int j = base + kk;
            s64s[j] = DINF;
            s32s[j] = FINF;
        }
        unsigned rem = validMask;
        unsigned scanned = 0;
        double minv = 0.0;
        float minv32 = 0.0f;
        int i = cur;
        float u32i = u32s[cur];
        int nSR = 0;
        int sink = -1;
        __syncwarp();

        while (true) {
            if (lane == 0) SRs[nSR] = i;
            nSR++;
            float dd32 = minv32 - u32i;
            const float* crow = costB + (size_t)i * NPAD + base;

            float4 c4[4];
            c4[0] = __ldg((const float4*)(crow + 0));
            c4[1] = __ldg((const float4*)(crow + 4));
            c4[2] = __ldg((const float4*)(crow + 8));
            c4[3] = __ldg((const float4*)(crow + 12));

            // fp32 sweep over owned columns; build candidate mask + packed key
            float se[16];
            unsigned candMask = 0;
            unsigned bestKey = 0xffffffffu;
            #pragma unroll
            for (int q = 0; q < 4; q++) {
                float4 vv = *(const float4*)(v32s + base + q * 4);
                float4 sv = *(const float4*)(s32s + base + q * 4);
                float cA[4] = {c4[q].x, c4[q].y, c4[q].z, c4[q].w};
                float vA[4] = {vv.x, vv.y, vv.z, vv.w};
                float sA[4] = {sv.x, sv.y, sv.z, sv.w};
                #pragma unroll
                for (int e = 0; e < 4; e++) {
                    int kk = q * 4 + e;
                    float r = (cA[e] - vA[e]) + dd32;
                    bool remb = (rem >> kk) & 1u;
                    bool cand = remb && (r < sA[e] + MARGIN);
                    if (cand) candMask |= (1u << kk);
                    float s_eff = cand ? fminf(sA[e], r) : sA[e];
                    se[kk] = s_eff;
                    unsigned ub = __float_as_uint(s_eff);
                    unsigned tkey = ub ^ (((unsigned)((int)ub >> 31)) | 0x80000000u);
                    unsigned key = (tkey & 0xfffffe00u) | (unsigned)(base + kk);
                    bestKey = min(bestKey, key);
                }
            }
            // exact fp64 updates for candidates only
            if (candMask) {
                double dd = minv - u64s[i];
                do {
                    int kk = __ffs(candMask) - 1;
                    candMask &= candMask - 1;
                    int j = base + kk;
                    double c64 = (double)__ldg(crow + kk);
                    double r = (c64 - v64s[j]) + dd;
                    if (r < s64s[j]) {
                        s64s[j] = r;
                        float rf = (float)r;
                        s32s[j] = rf;
                        paths[j] = i;
                        unsigned ub = __float_as_uint(rf);
                        unsigned tkey = ub ^ (((unsigned)((int)ub >> 31)) | 0x80000000u);
                        unsigned key = (tkey & 0xfffffe00u) | (unsigned)j;
                        bestKey = min(bestKey, key);
                    }
                } while (candMask);
            }
            // one REDUX: approximate min value + approximate argmin column
            unsigned mk = __reduce_min_sync(FULLMASK, bestKey);
            int jm_a = (int)(mk & 0x1ffu);
            unsigned tval = mk & 0xfffffe00u;
            float m32 = (tval & 0x80000000u) ? __uint_as_float(tval & 0x7fffffffu)
                                             : __uint_as_float(~tval);
            // one LDS.64: predicted next row + its u32; prefetch its row
            long long pr = rcu[jm_a];
            int r4c_a = (int)pr;
            unsigned ub_a = (unsigned)(((unsigned long long)pr) >> 32);
            if (r4c_a >= 0) {
                const float* pf = costB + (size_t)r4c_a * NPAD + base;
                asm volatile("prefetch.global.L1 [%0];" :: "l"(pf));
            }
            // exact resolution among columns within threshold
            float thr = fmaf(6.2e-5f, fabsf(m32), m32 + MARGIN);
            unsigned resMask = 0;
            #pragma unroll
            for (int kk = 0; kk < 16; kk++) {
                if (se[kk] <= thr) resMask |= (1u << kk);
            }
            resMask &= rem;
            double bestV = DINF;
            int bestJ = 0x7fffffff;
            while (resMask) {
                int kk = __ffs(resMask) - 1;
                resMask &= resMask - 1;
                int j = base + kk;
                double sv = s64s[j];
                if (sv < bestV) { bestV = sv; bestJ = j; }  // ascending j
            }
            unsigned bal = __ballot_sync(FULLMASK, bestJ != 0x7fffffff);
            int jm;
            if (__popc(bal) == 1) {
                int src = __ffs(bal) - 1;
                minv = __shfl_sync(FULLMASK, bestV, src);
                jm   = __shfl_sync(FULLMASK, bestJ, src);
            } else {
                #pragma unroll
                for (int off = 16; off > 0; off >>= 1) {
                    double ov = __shfl_down_sync(FULLMASK, bestV, off);
                    int    oj = __shfl_down_sync(FULLMASK, bestJ, off);
                    if (ov < bestV || (ov == bestV && oj < bestJ)) { bestV = ov; bestJ = oj; }
                }
                minv = __shfl_sync(FULLMASK, bestV, 0);
                jm   = __shfl_sync(FULLMASK, bestJ, 0);
            }
            if (jm > 0x1ff) { sink = -1; break; }   // defensive
            minv32 = (float)minv;
            // remove column jm
            if (lane == (jm >> 4)) {
                rem &= ~(1u << (jm & 15));
                scanned |= (1u << (jm & 15));
                s32s[jm] = FINF;
            }
            int r4c;
            unsigned ubx;
            if (jm == jm_a) {
                r4c = r4c_a;
                ubx = ub_a;
            } else {
                long long pr2 = rcu[jm];
                r4c = (int)pr2;
                ubx = (unsigned)(((unsigned long long)pr2) >> 32);
            }
            if (r4c < 0) { sink = jm; break; }
            i = r4c;
            u32i = __uint_as_float(ubx);
        }
        __syncwarp();
        if (sink < 0) continue;       // defensive (never taken in valid runs)

        // dual updates (exact fp64) + rcu refresh for scanned matched columns
        for (int s = lane; s < nSR; s += 32) {
            int row = SRs[s];
            double nu = u64s[row] +
                        ((s == 0) ? minv : (minv - s64s[col4rows[row]]));
            u64s[row] = nu;
            float nu32 = (float)nu;
            u32s[row] = nu32;
            if (s > 0) {
                rcu[col4rows[row]] = pack_rcu(nu32, row);
            }
        }
        {
            unsigned sm2 = scanned;
            while (sm2) {
                int kk = __ffs(sm2) - 1;
                sm2 &= sm2 - 1;
                int j = base + kk;
                double nv = v64s[j] - (minv - s64s[j]);
                v64s[j] = nv;
                v32s[j] = (float)nv;
            }
        }
        __syncwarp();
        // augment along alternating path; keep rcu consistent
        if (lane == 0) {
            int j = sink;
            while (true) {
                int ii = paths[j];
                rcu[j] = pack_rcu(u32s[ii], ii);
                int t = col4rows[ii];
                col4rows[ii] = j;
                j = t;
                if (ii == cur) break;
            }
        }
        __syncwarp();
    }

    for (int t = lane; t < MM; t += 32) g_map[b * MM + t] = col4rows[t];
}

// ---------------------------------------------------------------------------
// 4) extrapolation + output write
// ---------------------------------------------------------------------------
__global__ void extrap_kernel(const float* __restrict__ p1_boxes,
                              const float* __restrict__ p1_logits,
                              const float* __restrict__ p2_boxes,
                              const float* __restrict__ p2_logits,
                              const float* __restrict__ toff,
                              float* __restrict__ out) {
    int idx = blockIdx.x * blockDim.x + threadIdx.x;
    const int boxTotal = BB * MM * 4;
    const int logTotal = BB * MM * CC;
    if (idx < boxTotal) {
        int d = idx & 3;
        int bi = idx >> 2;
        int b = bi / MM;
        float first  = toff[b * 3 + 1] - toff[b * 3 + 0];
        float second = toff[b * 3 + 2] - toff[b * 3 + 1];
        float factor = second / first;
        int mcol = g_map[bi];
        float b2 = p2_boxes[idx];
        float c1 = p1_boxes[(b * NN + mcol) * 4 + d];
        float val = b2 + (b2 - c1) * factor;
        if (d >= 2) val = fmaxf(val, 0.0f);
        out[idx] = val;
    } else if (idx < boxTotal + logTotal) {
        int t = idx - boxTotal;
        int c = t % CC;
        int bi = t / CC;
        int b = bi / MM;
        int mcol = g_map[bi];
        float l2 = p2_logits[t];
        float l1 = p1_logits[(b * NN + mcol) * CC + c];
        out[idx] = 0.5f * (l2 + l1);
    }
}

// ---------------------------------------------------------------------------
extern "C" void kernel_launch(void* const* d_in, const int* in_sizes, int n_in,
                              void* d_out, int out_size) {
    const float* p1_boxes  = (const float*)d_in[0];
    const float* p1_logits = (const float*)d_in[1];
    const float* p2_boxes  = (const float*)d_in[2];
    const float* p2_logits = (const float*)d_in[3];
    const float* toff      = (const float*)d_in[4];
    float* out = (float*)d_out;

    {
        int total = BB * NN * CC + BB * MM * CC;
        int threads = 256;
        int blocks = (total + threads - 1) / threads;
        sigmoid_kernel<<<blocks, threads>>>(p1_logits, p2_logits);
    }
    {
        dim3 grid(NPAD / 32, (MM + 31) / 32, BB);
        dim3 block(32, 32);
        cost_kernel<<<grid, block>>>(p1_boxes, p2_boxes);
    }
    lsa_kernel<<<BB, 32>>>();
    {
        int total = BB * MM * 4 + BB * MM * CC;
        int threads = 256;
        int blocks = (total + threads - 1) / threads;
        extrap_kernel<<<blocks, threads>>>(p1_boxes, p1_logits, p2_boxes,
                                           p2_logits, toff, out);
    }
}